// round 10
// baseline (speedup 1.0000x reference)
#include <cuda_runtime.h>

#define NB   4096
#define NS   64
#define ND   128
#define NR_  16
#define NL   2
#define KTOT 2048     // NR_*ND
#define KSPLIT 4
#define BM   64
#define BN   128
#define BK   16

// ---------------- scratch (static device globals; no allocation) ----------------
__device__ float g_pre[(long long)NB * KTOT];          // 32 MB  [B, NR*D]
__device__ float g_node[NB * ND];                      // gathered node emb
__device__ float g_msgs_part[KSPLIT * NL * NB * ND];   // 16 MB  split-K partials
__device__ float g_x[NL * NB * ND];                    // per-layer outputs
__device__ float g_h[NB * ND];
__device__ float g_t[NB * ND];
__device__ float g_qkv[NL * NB * 3 * ND];              // 12.6 MB
__device__ float g_om[NB * ND];                        // mean-over-L attention out

// ---------------- packed f32x2 helpers ----------------
__device__ __forceinline__ unsigned long long dup2(float x) {
    unsigned long long r;
    unsigned int xi = __float_as_uint(x);
    asm("mov.b64 %0, {%1, %2};" : "=l"(r) : "r"(xi), "r"(xi));
    return r;
}
__device__ __forceinline__ void fma2(unsigned long long& acc, unsigned long long a,
                                     unsigned long long b) {
    asm("fma.rn.f32x2 %0, %1, %2, %0;" : "+l"(acc) : "l"(a), "l"(b));
}

// ---------------- K1: gather node + per-relation weighted neighbor sums ----------------
__global__ void k_gather_pre(const int* __restrict__ didx, const int* __restrict__ adjE,
                             const int* __restrict__ adjR, const float* __restrict__ ew,
                             const float* __restrict__ emb) {
    const int b = blockIdx.x, tid = threadIdx.x;  // 128 threads, one per d
    __shared__ float s_acc[NR_][ND];
    __shared__ int   s_ent[NS];
    __shared__ int   s_rel[NS];
    __shared__ float s_w[NS];
#pragma unroll
    for (int r = 0; r < NR_; r++) s_acc[r][tid] = 0.f;
    if (tid < NS) {
        s_ent[tid] = adjE[b * NS + tid];
        s_rel[tid] = adjR[b * NS + tid];
        s_w[tid]   = ew[b * NS + tid];
    }
    __syncthreads();
    for (int s0 = 0; s0 < NS; s0 += 8) {
        float v[8];
#pragma unroll
        for (int u = 0; u < 8; u++)
            v[u] = __ldg(emb + (long long)s_ent[s0 + u] * ND + tid);
#pragma unroll
        for (int u = 0; u < 8; u++)
            s_acc[s_rel[s0 + u]][tid] += s_w[s0 + u] * v[u];
    }
    g_node[b * ND + tid] = __ldg(emb + (long long)didx[b] * ND + tid);
    // each thread only ever touched its own column -> no sync needed
#pragma unroll
    for (int r = 0; r < NR_; r++)
        g_pre[(long long)b * KTOT + r * ND + tid] = s_acc[r][tid];
}

// ---------------- K2: msgs GEMM  C[l] = pre[B,2048] @ W[l][2048,128], split-K ----------------
__global__ void __launch_bounds__(128) k_gemm_msgs(const float* __restrict__ Wr) {
    const int mt = blockIdx.x, ksp = blockIdx.y, l = blockIdx.z;
    const int tid = threadIdx.x, tx = tid & 15, ty = tid >> 4;
    __shared__ __align__(16) float sA[BK][BM];
    __shared__ __align__(16) float sB[BK][BN];
    unsigned long long acc[4][8];
#pragma unroll
    for (int i = 0; i < 4; i++)
#pragma unroll
        for (int j = 0; j < 8; j++) acc[i][j] = 0ull;

    const float* Ab = g_pre + (long long)mt * BM * KTOT;
    const float* Wb = Wr + (long long)l * KTOT * ND;
    const int kbase = ksp * (KTOT / KSPLIT);

    for (int kc = 0; kc < KTOT / KSPLIT; kc += BK) {
        const int kg = kbase + kc;
        // A tile 64x16, transposed store
#pragma unroll
        for (int r = 0; r < 2; r++) {
            int f4 = tid + r * 128;
            int m = f4 >> 2, c4 = f4 & 3;
            float4 v = *reinterpret_cast<const float4*>(Ab + (long long)m * KTOT + kg + c4 * 4);
            sA[c4 * 4 + 0][m] = v.x; sA[c4 * 4 + 1][m] = v.y;
            sA[c4 * 4 + 2][m] = v.z; sA[c4 * 4 + 3][m] = v.w;
        }
        // B tile 16x128, direct
#pragma unroll
        for (int r = 0; r < 4; r++) {
            int f4 = tid + r * 128;
            int kk = f4 >> 5, c = f4 & 31;
            *reinterpret_cast<float4*>(&sB[kk][c * 4]) =
                *reinterpret_cast<const float4*>(Wb + (long long)(kg + kk) * ND + c * 4);
        }
        __syncthreads();
#pragma unroll
        for (int kk = 0; kk < BK; kk++) {
            unsigned long long ap[4];
#pragma unroll
            for (int i = 0; i < 4; i++)
                ap[i] = *reinterpret_cast<const unsigned long long*>(&sA[kk][ty * 8 + 2 * i]);
#pragma unroll
            for (int j = 0; j < 8; j++) {
                unsigned long long bd = dup2(sB[kk][tx + 16 * j]);
#pragma unroll
                for (int i = 0; i < 4; i++) fma2(acc[i][j], ap[i], bd);
            }
        }
        __syncthreads();
    }
    float* Cp = g_msgs_part + (long long)(ksp * NL + l) * (NB * ND) + (long long)mt * BM * ND;
#pragma unroll
    for (int i = 0; i < 4; i++) {
#pragma unroll
        for (int j = 0; j < 8; j++) {
            int m = ty * 8 + 2 * i;
            int n = tx + 16 * j;
            Cp[m * ND + n]       = __uint_as_float((unsigned)(acc[i][j] & 0xffffffffull));
            Cp[(m + 1) * ND + n] = __uint_as_float((unsigned)(acc[i][j] >> 32));
        }
    }
}

// ---------------- generic small GEMM: C[M,N] = A[M,128] @ W[N,128]^T + bias ----------------
__global__ void __launch_bounds__(128) k_gemm_small(const float* __restrict__ A,
                                                    const float* __restrict__ W,
                                                    const float* __restrict__ bias,
                                                    float* __restrict__ C, int ldC) {
    const int mt = blockIdx.x, nt = blockIdx.y;
    const int tid = threadIdx.x, tx = tid & 15, ty = tid >> 4;
    __shared__ __align__(16) float sA[BK][BM];
    __shared__ __align__(16) float sB[BK][BN];
    unsigned long long acc[4][8];
#pragma unroll
    for (int i = 0; i < 4; i++)
#pragma unroll
        for (int j = 0; j < 8; j++) acc[i][j] = 0ull;

    const float* Ab = A + (long long)mt * BM * ND;
    const float* Wb = W + (long long)nt * BN * ND;

    for (int kc = 0; kc < ND; kc += BK) {
        // A tile 64x16, transposed store
#pragma unroll
        for (int r = 0; r < 2; r++) {
            int f4 = tid + r * 128;
            int m = f4 >> 2, c4 = f4 & 3;
            float4 v = *reinterpret_cast<const float4*>(Ab + (long long)m * ND + kc + c4 * 4);
            sA[c4 * 4 + 0][m] = v.x; sA[c4 * 4 + 1][m] = v.y;
            sA[c4 * 4 + 2][m] = v.z; sA[c4 * 4 + 3][m] = v.w;
        }
        // W tile 128x16 (row = n, cols = k), transposed store -> sB[k][n]
#pragma unroll
        for (int r = 0; r < 4; r++) {
            int f4 = tid + r * 128;
            int n = f4 >> 2, c4 = f4 & 3;
            float4 v = *reinterpret_cast<const float4*>(Wb + (long long)n * ND + kc + c4 * 4);
            sB[c4 * 4 + 0][n] = v.x; sB[c4 * 4 + 1][n] = v.y;
            sB[c4 * 4 + 2][n] = v.z; sB[c4 * 4 + 3][n] = v.w;
        }
        __syncthreads();
#pragma unroll
        for (int kk = 0; kk < BK; kk++) {
            unsigned long long ap[4];
#pragma unroll
            for (int i = 0; i < 4; i++)
                ap[i] = *reinterpret_cast<const unsigned long long*>(&sA[kk][ty * 8 + 2 * i]);
#pragma unroll
            for (int j = 0; j < 8; j++) {
                unsigned long long bd = dup2(sB[kk][tx + 16 * j]);
#pragma unroll
                for (int i = 0; i < 4; i++) fma2(acc[i][j], ap[i], bd);
            }
        }
        __syncthreads();
    }
#pragma unroll
    for (int i = 0; i < 4; i++) {
#pragma unroll
        for (int j = 0; j < 8; j++) {
            int m = ty * 8 + 2 * i;
            int n = nt * BN + tx + 16 * j;
            float bs = bias[n];
            float lo = __uint_as_float((unsigned)(acc[i][j] & 0xffffffffull)) + bs;
            float hi = __uint_as_float((unsigned)(acc[i][j] >> 32)) + bs;
            C[(long long)(mt * BM + m) * ldC + n]     = lo;
            C[(long long)(mt * BM + m + 1) * ldC + n] = hi;
        }
    }
}

// ---------------- h = relu(node + msgs + t1)   (reduces split-K partials inline) ----------------
__global__ void k_hrelu(const float* __restrict__ node, int l) {
    const int i = blockIdx.x * 256 + threadIdx.x;
    float m = g_msgs_part[(0 * NL + l) * (NB * ND) + i]
            + g_msgs_part[(1 * NL + l) * (NB * ND) + i]
            + g_msgs_part[(2 * NL + l) * (NB * ND) + i]
            + g_msgs_part[(3 * NL + l) * (NB * ND) + i];
    float v = node[i] + g_t[i] + m;
    g_h[i] = v > 0.f ? v : 0.f;
}

// ---------------- LayerNorm (optional residual add) ----------------
__global__ void k_ln(const float* __restrict__ x, const float* __restrict__ res,
                     const float* __restrict__ gam, const float* __restrict__ bet,
                     float* __restrict__ out) {
    const int row = blockIdx.x, tid = threadIdx.x;  // 128 threads
    float v = x[row * ND + tid];
    if (res) v += res[row * ND + tid];
    float a = v, b = v * v;
#pragma unroll
    for (int o = 16; o; o >>= 1) {
        a += __shfl_xor_sync(0xffffffffu, a, o);
        b += __shfl_xor_sync(0xffffffffu, b, o);
    }
    __shared__ float s1[4], s2[4];
    if ((tid & 31) == 0) { s1[tid >> 5] = a; s2[tid >> 5] = b; }
    __syncthreads();
    float m = (s1[0] + s1[1] + s1[2] + s1[3]) * (1.f / ND);
    float q = (s2[0] + s2[1] + s2[2] + s2[3]) * (1.f / ND);
    float var = q - m * m;
    out[row * ND + tid] = (v - m) * rsqrtf(var + 1e-5f) * gam[tid] + bet[tid];
}

// ---------------- attention over L=2 positions, H=4 heads of 32; outputs mean over L ----------------
__global__ void k_attn() {
    const int b = blockIdx.x, tid = threadIdx.x;
    const int h = tid >> 5, d = tid & 31;
    const float* r0 = g_qkv + (long long)b * 384 + h * 32 + d;
    const float* r1 = g_qkv + (long long)(NB + b) * 384 + h * 32 + d;
    float Q0 = r0[0], K0 = r0[128], V0 = r0[256];
    float Q1 = r1[0], K1 = r1[128], V1 = r1[256];
    float s00 = Q0 * K0, s01 = Q0 * K1, s10 = Q1 * K0, s11 = Q1 * K1;
#pragma unroll
    for (int o = 16; o; o >>= 1) {
        s00 += __shfl_xor_sync(0xffffffffu, s00, o);
        s01 += __shfl_xor_sync(0xffffffffu, s01, o);
        s10 += __shfl_xor_sync(0xffffffffu, s10, o);
        s11 += __shfl_xor_sync(0xffffffffu, s11, o);
    }
    const float sc = 0.17677669529663687f;  // 1/sqrt(32)
    s00 *= sc; s01 *= sc; s10 *= sc; s11 *= sc;
    float m0 = fmaxf(s00, s01), m1 = fmaxf(s10, s11);
    float e00 = __expf(s00 - m0), e01 = __expf(s01 - m0);
    float e10 = __expf(s10 - m1), e11 = __expf(s11 - m1);
    float o0 = (e00 * V0 + e01 * V1) / (e00 + e01);
    float o1 = (e10 * V0 + e11 * V1) / (e10 + e11);
    g_om[(long long)b * ND + h * 32 + d] = 0.5f * (o0 + o1);
}

// ---------------- launch ----------------
extern "C" void kernel_launch(void* const* d_in, const int* in_sizes, int n_in,
                              void* d_out, int out_size) {
    const int*   didx  = (const int*)d_in[0];
    const int*   adjE  = (const int*)d_in[1];
    const int*   adjR  = (const int*)d_in[2];
    const float* ew    = (const float*)d_in[3];
    const float* emb   = (const float*)d_in[4];
    const float* Wr    = (const float*)d_in[5];
    const float* resw  = (const float*)d_in[6];
    const float* resb  = (const float*)d_in[7];
    const float* projw = (const float*)d_in[8];
    const float* projb = (const float*)d_in[9];
    const float* lng   = (const float*)d_in[10];
    const float* lnb   = (const float*)d_in[11];
    const float* ipw   = (const float*)d_in[12];
    const float* ipb   = (const float*)d_in[13];
    const float* opw   = (const float*)d_in[14];
    const float* opb   = (const float*)d_in[15];
    const float* flng  = (const float*)d_in[16];
    const float* flnb  = (const float*)d_in[17];

    float *p_node, *p_x, *p_h, *p_t, *p_qkv, *p_om;
    cudaGetSymbolAddress((void**)&p_node, g_node);
    cudaGetSymbolAddress((void**)&p_x,    g_x);
    cudaGetSymbolAddress((void**)&p_h,    g_h);
    cudaGetSymbolAddress((void**)&p_t,    g_t);
    cudaGetSymbolAddress((void**)&p_qkv,  g_qkv);
    cudaGetSymbolAddress((void**)&p_om,   g_om);

    // 1. gather + per-relation pre-aggregation
    k_gather_pre<<<NB, 128>>>(didx, adjE, adjR, ew, emb);

    // 2. msgs for both layers, split-K=4
    k_gemm_msgs<<<dim3(NB / BM, KSPLIT, NL), 128>>>(Wr);

    // 3. RGCN layers (sequential)
    for (int l = 0; l < NL; l++) {
        const float* nodeIn = (l == 0) ? p_node : (p_x + (long long)(l - 1) * NB * ND);
        k_gemm_small<<<dim3(NB / BM, 1), 128>>>(nodeIn, resw + (long long)l * ND * ND,
                                                resb + l * ND, p_t, ND);
        k_hrelu<<<(NB * ND) / 256, 256>>>(nodeIn, l);
        k_gemm_small<<<dim3(NB / BM, 1), 128>>>(p_h, projw + (long long)l * ND * ND,
                                                projb + l * ND, p_t, ND);
        k_ln<<<NB, 128>>>(p_t, nodeIn, lng + l * ND, lnb + l * ND,
                          p_x + (long long)l * NB * ND);
    }

    // 4. qkv projection over both layers' outputs: [2B,128] x [128,384]^T
    k_gemm_small<<<dim3((NL * NB) / BM, 3), 128>>>(p_x, ipw, ipb, p_qkv, 3 * ND);

    // 5. tiny L=2 attention + mean over L
    k_attn<<<NB, 128>>>();

    // 6. out projection (mean commuted before projection) + final LN
    k_gemm_small<<<dim3(NB / BM, 1), 128>>>(p_om, opw, opb, p_t, ND);
    k_ln<<<NB, 128>>>(p_t, nullptr, flng, flnb, (float*)d_out);
}

// round 11
// speedup vs baseline: 1.0128x; 1.0128x over previous
#include <cuda_runtime.h>

#define NB   4096
#define NS   64
#define ND   128
#define NR_  16
#define NL   2
#define KTOT 2048     // NR_*ND
#define KSPLIT 4
#define BM   64
#define BN   128
#define BK   16

// ---------------- scratch (static device globals; no allocation) ----------------
__device__ float g_pre[(long long)NB * KTOT];          // 32 MB  [B, NR*D]
__device__ float g_node[NB * ND];                      // gathered node emb
__device__ float g_msgs_part[KSPLIT * NL * NB * ND];   // 16 MB  split-K partials
__device__ float g_x[NL * NB * ND];                    // per-layer outputs
__device__ float g_h[NB * ND];
__device__ float g_t[NB * ND];
__device__ float g_qkv[NL * NB * 3 * ND];              // 12.6 MB
__device__ float g_om[NB * ND];                        // mean-over-L attention out

// ---------------- packed f32x2 helpers ----------------
__device__ __forceinline__ unsigned long long dup2(float x) {
    unsigned long long r;
    unsigned int xi = __float_as_uint(x);
    asm("mov.b64 %0, {%1, %2};" : "=l"(r) : "r"(xi), "r"(xi));
    return r;
}
__device__ __forceinline__ void fma2(unsigned long long& acc, unsigned long long a,
                                     unsigned long long b) {
    asm("fma.rn.f32x2 %0, %1, %2, %0;" : "+l"(acc) : "l"(a), "l"(b));
}

// ---------------- K1: gather node + per-relation weighted neighbor sums ----------------
__global__ void k_gather_pre(const int* __restrict__ didx, const int* __restrict__ adjE,
                             const int* __restrict__ adjR, const float* __restrict__ ew,
                             const float* __restrict__ emb) {
    const int b = blockIdx.x, tid = threadIdx.x;  // 128 threads, one per d
    __shared__ float s_acc[NR_][ND];
    __shared__ int   s_ent[NS];
    __shared__ int   s_rel[NS];
    __shared__ float s_w[NS];
#pragma unroll
    for (int r = 0; r < NR_; r++) s_acc[r][tid] = 0.f;
    if (tid < NS) {
        s_ent[tid] = adjE[b * NS + tid];
        s_rel[tid] = adjR[b * NS + tid];
        s_w[tid]   = ew[b * NS + tid];
    }
    __syncthreads();
    for (int s0 = 0; s0 < NS; s0 += 8) {
        float v[8];
#pragma unroll
        for (int u = 0; u < 8; u++)
            v[u] = __ldg(emb + (long long)s_ent[s0 + u] * ND + tid);
#pragma unroll
        for (int u = 0; u < 8; u++)
            s_acc[s_rel[s0 + u]][tid] += s_w[s0 + u] * v[u];
    }
    g_node[b * ND + tid] = __ldg(emb + (long long)didx[b] * ND + tid);
    // each thread only ever touched its own column -> no sync needed
#pragma unroll
    for (int r = 0; r < NR_; r++)
        g_pre[(long long)b * KTOT + r * ND + tid] = s_acc[r][tid];
}

// ---------------- K2: msgs GEMM  C[l] = pre[B,2048] @ W[l][2048,128], split-K ----------------
__global__ void __launch_bounds__(128) k_gemm_msgs(const float* __restrict__ Wr) {
    const int mt = blockIdx.x, ksp = blockIdx.y, l = blockIdx.z;
    const int tid = threadIdx.x, tx = tid & 15, ty = tid >> 4;
    __shared__ __align__(16) float sA[BK][BM];
    __shared__ __align__(16) float sB[BK][BN];
    unsigned long long acc[4][8];
#pragma unroll
    for (int i = 0; i < 4; i++)
#pragma unroll
        for (int j = 0; j < 8; j++) acc[i][j] = 0ull;

    const float* Ab = g_pre + (long long)mt * BM * KTOT;
    const float* Wb = Wr + (long long)l * KTOT * ND;
    const int kbase = ksp * (KTOT / KSPLIT);

    for (int kc = 0; kc < KTOT / KSPLIT; kc += BK) {
        const int kg = kbase + kc;
        // A tile 64x16, transposed store
#pragma unroll
        for (int r = 0; r < 2; r++) {
            int f4 = tid + r * 128;
            int m = f4 >> 2, c4 = f4 & 3;
            float4 v = *reinterpret_cast<const float4*>(Ab + (long long)m * KTOT + kg + c4 * 4);
            sA[c4 * 4 + 0][m] = v.x; sA[c4 * 4 + 1][m] = v.y;
            sA[c4 * 4 + 2][m] = v.z; sA[c4 * 4 + 3][m] = v.w;
        }
        // B tile 16x128, direct
#pragma unroll
        for (int r = 0; r < 4; r++) {
            int f4 = tid + r * 128;
            int kk = f4 >> 5, c = f4 & 31;
            *reinterpret_cast<float4*>(&sB[kk][c * 4]) =
                *reinterpret_cast<const float4*>(Wb + (long long)(kg + kk) * ND + c * 4);
        }
        __syncthreads();
#pragma unroll
        for (int kk = 0; kk < BK; kk++) {
            unsigned long long ap[4];
#pragma unroll
            for (int i = 0; i < 4; i++)
                ap[i] = *reinterpret_cast<const unsigned long long*>(&sA[kk][ty * 8 + 2 * i]);
#pragma unroll
            for (int j = 0; j < 8; j++) {
                unsigned long long bd = dup2(sB[kk][tx + 16 * j]);
#pragma unroll
                for (int i = 0; i < 4; i++) fma2(acc[i][j], ap[i], bd);
            }
        }
        __syncthreads();
    }
    float* Cp = g_msgs_part + (long long)(ksp * NL + l) * (NB * ND) + (long long)mt * BM * ND;
#pragma unroll
    for (int i = 0; i < 4; i++) {
#pragma unroll
        for (int j = 0; j < 8; j++) {
            int m = ty * 8 + 2 * i;
            int n = tx + 16 * j;
            Cp[m * ND + n]       = __uint_as_float((unsigned)(acc[i][j] & 0xffffffffull));
            Cp[(m + 1) * ND + n] = __uint_as_float((unsigned)(acc[i][j] >> 32));
        }
    }
}

// ---------------- generic small GEMM: C[M,N] = A[M,128] @ W[N,128]^T + bias ----------------
__global__ void __launch_bounds__(128) k_gemm_small(const float* __restrict__ A,
                                                    const float* __restrict__ W,
                                                    const float* __restrict__ bias,
                                                    float* __restrict__ C, int ldC) {
    const int mt = blockIdx.x, nt = blockIdx.y;
    const int tid = threadIdx.x, tx = tid & 15, ty = tid >> 4;
    __shared__ __align__(16) float sA[BK][BM];
    __shared__ __align__(16) float sB[BK][BN];
    unsigned long long acc[4][8];
#pragma unroll
    for (int i = 0; i < 4; i++)
#pragma unroll
        for (int j = 0; j < 8; j++) acc[i][j] = 0ull;

    const float* Ab = A + (long long)mt * BM * ND;
    const float* Wb = W + (long long)nt * BN * ND;

    for (int kc = 0; kc < ND; kc += BK) {
        // A tile 64x16, transposed store
#pragma unroll
        for (int r = 0; r < 2; r++) {
            int f4 = tid + r * 128;
            int m = f4 >> 2, c4 = f4 & 3;
            float4 v = *reinterpret_cast<const float4*>(Ab + (long long)m * ND + kc + c4 * 4);
            sA[c4 * 4 + 0][m] = v.x; sA[c4 * 4 + 1][m] = v.y;
            sA[c4 * 4 + 2][m] = v.z; sA[c4 * 4 + 3][m] = v.w;
        }
        // W tile 128x16 (row = n, cols = k), transposed store -> sB[k][n]
#pragma unroll
        for (int r = 0; r < 4; r++) {
            int f4 = tid + r * 128;
            int n = f4 >> 2, c4 = f4 & 3;
            float4 v = *reinterpret_cast<const float4*>(Wb + (long long)n * ND + kc + c4 * 4);
            sB[c4 * 4 + 0][n] = v.x; sB[c4 * 4 + 1][n] = v.y;
            sB[c4 * 4 + 2][n] = v.z; sB[c4 * 4 + 3][n] = v.w;
        }
        __syncthreads();
#pragma unroll
        for (int kk = 0; kk < BK; kk++) {
            unsigned long long ap[4];
#pragma unroll
            for (int i = 0; i < 4; i++)
                ap[i] = *reinterpret_cast<const unsigned long long*>(&sA[kk][ty * 8 + 2 * i]);
#pragma unroll
            for (int j = 0; j < 8; j++) {
                unsigned long long bd = dup2(sB[kk][tx + 16 * j]);
#pragma unroll
                for (int i = 0; i < 4; i++) fma2(acc[i][j], ap[i], bd);
            }
        }
        __syncthreads();
    }
#pragma unroll
    for (int i = 0; i < 4; i++) {
#pragma unroll
        for (int j = 0; j < 8; j++) {
            int m = ty * 8 + 2 * i;
            int n = nt * BN + tx + 16 * j;
            float bs = bias[n];
            float lo = __uint_as_float((unsigned)(acc[i][j] & 0xffffffffull)) + bs;
            float hi = __uint_as_float((unsigned)(acc[i][j] >> 32)) + bs;
            C[(long long)(mt * BM + m) * ldC + n]     = lo;
            C[(long long)(mt * BM + m + 1) * ldC + n] = hi;
        }
    }
}

// ---------------- h = relu(node + msgs + t1)   (reduces split-K partials inline) ----------------
__global__ void k_hrelu(const float* __restrict__ node, int l) {
    const int i = blockIdx.x * 256 + threadIdx.x;
    float m = g_msgs_part[(0 * NL + l) * (NB * ND) + i]
            + g_msgs_part[(1 * NL + l) * (NB * ND) + i]
            + g_msgs_part[(2 * NL + l) * (NB * ND) + i]
            + g_msgs_part[(3 * NL + l) * (NB * ND) + i];
    float v = node[i] + g_t[i] + m;
    g_h[i] = v > 0.f ? v : 0.f;
}

// ---------------- LayerNorm (optional residual add) ----------------
__global__ void k_ln(const float* __restrict__ x, const float* __restrict__ res,
                     const float* __restrict__ gam, const float* __restrict__ bet,
                     float* __restrict__ out) {
    const int row = blockIdx.x, tid = threadIdx.x;  // 128 threads
    float v = x[row * ND + tid];
    if (res) v += res[row * ND + tid];
    float a = v, b = v * v;
#pragma unroll
    for (int o = 16; o; o >>= 1) {
        a += __shfl_xor_sync(0xffffffffu, a, o);
        b += __shfl_xor_sync(0xffffffffu, b, o);
    }
    __shared__ float s1[4], s2[4];
    if ((tid & 31) == 0) { s1[tid >> 5] = a; s2[tid >> 5] = b; }
    __syncthreads();
    float m = (s1[0] + s1[1] + s1[2] + s1[3]) * (1.f / ND);
    float q = (s2[0] + s2[1] + s2[2] + s2[3]) * (1.f / ND);
    float var = q - m * m;
    out[row * ND + tid] = (v - m) * rsqrtf(var + 1e-5f) * gam[tid] + bet[tid];
}

// ---------------- attention over L=2 positions, H=4 heads of 32; outputs mean over L ----------------
__global__ void k_attn() {
    const int b = blockIdx.x, tid = threadIdx.x;
    const int h = tid >> 5, d = tid & 31;
    const float* r0 = g_qkv + (long long)b * 384 + h * 32 + d;
    const float* r1 = g_qkv + (long long)(NB + b) * 384 + h * 32 + d;
    float Q0 = r0[0], K0 = r0[128], V0 = r0[256];
    float Q1 = r1[0], K1 = r1[128], V1 = r1[256];
    float s00 = Q0 * K0, s01 = Q0 * K1, s10 = Q1 * K0, s11 = Q1 * K1;
#pragma unroll
    for (int o = 16; o; o >>= 1) {
        s00 += __shfl_xor_sync(0xffffffffu, s00, o);
        s01 += __shfl_xor_sync(0xffffffffu, s01, o);
        s10 += __shfl_xor_sync(0xffffffffu, s10, o);
        s11 += __shfl_xor_sync(0xffffffffu, s11, o);
    }
    const float sc = 0.17677669529663687f;  // 1/sqrt(32)
    s00 *= sc; s01 *= sc; s10 *= sc; s11 *= sc;
    float m0 = fmaxf(s00, s01), m1 = fmaxf(s10, s11);
    float e00 = __expf(s00 - m0), e01 = __expf(s01 - m0);
    float e10 = __expf(s10 - m1), e11 = __expf(s11 - m1);
    float o0 = (e00 * V0 + e01 * V1) / (e00 + e01);
    float o1 = (e10 * V0 + e11 * V1) / (e10 + e11);
    g_om[(long long)b * ND + h * 32 + d] = 0.5f * (o0 + o1);
}

// ---------------- launch ----------------
extern "C" void kernel_launch(void* const* d_in, const int* in_sizes, int n_in,
                              void* d_out, int out_size) {
    const int*   didx  = (const int*)d_in[0];
    const int*   adjE  = (const int*)d_in[1];
    const int*   adjR  = (const int*)d_in[2];
    const float* ew    = (const float*)d_in[3];
    const float* emb   = (const float*)d_in[4];
    const float* Wr    = (const float*)d_in[5];
    const float* resw  = (const float*)d_in[6];
    const float* resb  = (const float*)d_in[7];
    const float* projw = (const float*)d_in[8];
    const float* projb = (const float*)d_in[9];
    const float* lng   = (const float*)d_in[10];
    const float* lnb   = (const float*)d_in[11];
    const float* ipw   = (const float*)d_in[12];
    const float* ipb   = (const float*)d_in[13];
    const float* opw   = (const float*)d_in[14];
    const float* opb   = (const float*)d_in[15];
    const float* flng  = (const float*)d_in[16];
    const float* flnb  = (const float*)d_in[17];

    float *p_node, *p_x, *p_h, *p_t, *p_qkv, *p_om;
    cudaGetSymbolAddress((void**)&p_node, g_node);
    cudaGetSymbolAddress((void**)&p_x,    g_x);
    cudaGetSymbolAddress((void**)&p_h,    g_h);
    cudaGetSymbolAddress((void**)&p_t,    g_t);
    cudaGetSymbolAddress((void**)&p_qkv,  g_qkv);
    cudaGetSymbolAddress((void**)&p_om,   g_om);

    // 1. gather + per-relation pre-aggregation
    k_gather_pre<<<NB, 128>>>(didx, adjE, adjR, ew, emb);

    // 2. msgs for both layers, split-K=4
    k_gemm_msgs<<<dim3(NB / BM, KSPLIT, NL), 128>>>(Wr);

    // 3. RGCN layers (sequential)
    for (int l = 0; l < NL; l++) {
        const float* nodeIn = (l == 0) ? p_node : (p_x + (long long)(l - 1) * NB * ND);
        k_gemm_small<<<dim3(NB / BM, 1), 128>>>(nodeIn, resw + (long long)l * ND * ND,
                                                resb + l * ND, p_t, ND);
        k_hrelu<<<(NB * ND) / 256, 256>>>(nodeIn, l);
        k_gemm_small<<<dim3(NB / BM, 1), 128>>>(p_h, projw + (long long)l * ND * ND,
                                                projb + l * ND, p_t, ND);
        k_ln<<<NB, 128>>>(p_t, nodeIn, lng + l * ND, lnb + l * ND,
                          p_x + (long long)l * NB * ND);
    }

    // 4. qkv projection over both layers' outputs: [2B,128] x [128,384]^T
    k_gemm_small<<<dim3((NL * NB) / BM, 3), 128>>>(p_x, ipw, ipb, p_qkv, 3 * ND);

    // 5. tiny L=2 attention + mean over L
    k_attn<<<NB, 128>>>();

    // 6. out projection (mean commuted before projection) + final LN
    k_gemm_small<<<dim3(NB / BM, 1), 128>>>(p_om, opw, opb, p_t, ND);
    k_ln<<<NB, 128>>>(p_t, nullptr, flng, flnb, (float*)d_out);
}